// round 12
// baseline (speedup 1.0000x reference)
#include <cuda_runtime.h>
#include <cuda_bf16.h>
#include <math.h>

// ---------------- problem constants ----------------
#define TN   4096
#define DN   128
#define HN   512
#define EN   256
#define WN   4
#define G3H  1536

// scan config
#define NC   64       // persistent CTAs
#define NTH  512      // 16 warps
#define CP   8        // H-columns owned per CTA (NC*CP = 512)
#define RING 8        // lookback ring (word length <= 6 -> s >= t-5)

// ---------------- device scratch (static; no cudaMalloc) ----------------
__device__ float g_px [(size_t)TN * G3H];         // x@W + b
__device__ float g_pxa[(size_t)TN * HN];          // x@Wa + ba
__device__ float g_pxw[(size_t)TN * WN * G3H];    // emb[wid]@Ww + bw (active only)
__device__ float g_cw [WN * HN];                  // per-step c_w exchange
__device__ __align__(256) int g_flags[NC];        // per-CTA epoch flags (contiguous)
__device__ int   g_nact;                          // number of active (t,w)
__device__ int   g_gather [TN * WN];              // active -> word id (emb row)
__device__ int   g_scatter[TN * WN];              // active -> flat (t*WN+w)
__device__ unsigned char g_mask[TN * WN];         // decoded bool mask

// ---------------- helpers ----------------
__device__ __forceinline__ int ld_rlx(const int* p) {
    int v;
    asm volatile("ld.relaxed.gpu.global.b32 %0, [%1];" : "=r"(v) : "l"(p));
    return v;
}
__device__ __forceinline__ void st_rel(int* p, int v) {
    asm volatile("st.release.gpu.global.b32 [%0], %1;" :: "l"(p), "r"(v) : "memory");
}
__device__ __forceinline__ void fence_acq() {
    asm volatile("fence.acq_rel.gpu;" ::: "memory");
}
__device__ __forceinline__ void cp16(void* dst, const void* src) {
    unsigned s = (unsigned)__cvta_generic_to_shared(dst);
    asm volatile("cp.async.ca.shared.global [%0], [%1], 16;" :: "r"(s), "l"(src));
}
__device__ __forceinline__ void cp4(void* dst, const void* src) {
    unsigned s = (unsigned)__cvta_generic_to_shared(dst);
    asm volatile("cp.async.ca.shared.global [%0], [%1], 4;" :: "r"(s), "l"(src));
}
__device__ __forceinline__ void cp_commit() { asm volatile("cp.async.commit_group;"); }
__device__ __forceinline__ void cp_waitall() { asm volatile("cp.async.wait_group 0;"); }

__device__ __forceinline__ float sigm_f(float v) { return 1.0f / (1.0f + __expf(-v)); }
__device__ __forceinline__ float tanh_f(float v) {
    v = fminf(fmaxf(v, -10.0f), 10.0f);
    float e = __expf(-2.0f * v);
    return (1.0f - e) / (1.0f + e);
}

// all-poll flag barrier (tid0 of each CTA). Arrivals are plain release stores
// to DISTINCT words (no LTS atomic serialization). Each waiter polls all 64
// flags with independent relaxed loads (full MLP: one ~L2-latency per round),
// then one acquire fence orders the subsequent data reads.
__device__ __forceinline__ void gbar(int cta, int epoch) {
    st_rel(&g_flags[cta], epoch);
    for (;;) {
        int mn = 0x7fffffff;
        #pragma unroll
        for (int i = 0; i < NC; i++) {
            int v = ld_rlx(&g_flags[i]);
            mn = (v < mn) ? v : mn;
        }
        if (mn >= epoch) break;
    }
    fence_acq();
}

// ---------------- prep: zero counters + decode mask dtype ----------------
__global__ void prep_kernel(const unsigned char* __restrict__ raw) {
    __shared__ int nz[4];
    int tid = threadIdx.x;
    if (tid == 0) g_nact = 0;
    if (tid < NC) g_flags[tid] = 0;
    if (tid < 4) nz[tid] = 0;
    __syncthreads();
    for (int i = tid; i < TN * WN; i += blockDim.x)
        if (raw[i]) atomicOr(&nz[i & 3], 1);
    __syncthreads();
    int mode;
    if (nz[0]) mode = (nz[1] | nz[2] | nz[3]) ? 0 : 1;   // 0=u8, 1=i32
    else       mode = (nz[2] | nz[3]) ? 2 : 0;           // 2=f32
    for (int i = tid; i < TN * WN; i += blockDim.x) {
        unsigned char m;
        if (mode == 0)      m = (raw[i] != 0);
        else if (mode == 1) m = (((const int*)raw)[i] != 0);
        else                m = (((const float*)raw)[i] != 0.0f);
        g_mask[i] = m;
    }
}

// ---------------- build compact active-word list ----------------
__global__ void build_active_kernel(const int* __restrict__ word_ids) {
    int i = blockIdx.x * blockDim.x + threadIdx.x;
    if (i < TN * WN && g_mask[i]) {
        int pos = atomicAdd(&g_nact, 1);
        g_gather[pos]  = word_ids[i];
        g_scatter[pos] = i;
    }
}

// ---------------- fp32 SGEMM: C = (gather?)A @ B + bias ----------------
__global__ void __launch_bounds__(256) sgemm_kernel(
    const float* __restrict__ A, const float* __restrict__ B,
    const float* __restrict__ bias,
    int M, int N, int K, int use_gather, int dst_sel)
{
    __shared__ float As[16][68];
    __shared__ float Bs[16][68];

    float* C = (dst_sel == 0) ? g_px : (dst_sel == 1) ? g_pxa : g_pxw;
    int Meff = use_gather ? g_nact : M;
    int row0 = blockIdx.y * 64;
    int col0 = blockIdx.x * 64;
    if (row0 >= Meff) return;

    int tid = threadIdx.x;
    int tx = tid & 15, ty = tid >> 4;

    int arow_l = tid >> 2;
    int ak0    = (tid & 3) * 4;
    int arow_g = row0 + arow_l;
    bool a_ok  = (arow_g < Meff);
    const float* Arow = A;
    if (a_ok) {
        int r = use_gather ? g_gather[arow_g] : arow_g;
        Arow = A + (size_t)r * K;
    }
    int bk  = tid >> 4;
    int bc0 = (tid & 15) * 4;

    float acc[4][4];
    #pragma unroll
    for (int i = 0; i < 4; i++)
        #pragma unroll
        for (int j = 0; j < 4; j++) acc[i][j] = 0.0f;

    for (int k0 = 0; k0 < K; k0 += 16) {
        float4 av = make_float4(0.f, 0.f, 0.f, 0.f);
        if (a_ok) av = *reinterpret_cast<const float4*>(Arow + k0 + ak0);
        As[ak0 + 0][arow_l] = av.x;
        As[ak0 + 1][arow_l] = av.y;
        As[ak0 + 2][arow_l] = av.z;
        As[ak0 + 3][arow_l] = av.w;
        float4 bv = *reinterpret_cast<const float4*>(B + (size_t)(k0 + bk) * N + col0 + bc0);
        *reinterpret_cast<float4*>(&Bs[bk][bc0]) = bv;
        __syncthreads();
        #pragma unroll
        for (int kk = 0; kk < 16; kk++) {
            float4 a4 = *reinterpret_cast<const float4*>(&As[kk][ty * 4]);
            float4 b4 = *reinterpret_cast<const float4*>(&Bs[kk][tx * 4]);
            float aa[4] = {a4.x, a4.y, a4.z, a4.w};
            float bb[4] = {b4.x, b4.y, b4.z, b4.w};
            #pragma unroll
            for (int i = 0; i < 4; i++)
                #pragma unroll
                for (int j = 0; j < 4; j++)
                    acc[i][j] = fmaf(aa[i], bb[j], acc[i][j]);
        }
        __syncthreads();
    }
    #pragma unroll
    for (int i = 0; i < 4; i++) {
        int r = row0 + ty * 4 + i;
        if (r < Meff) {
            int cr = use_gather ? g_scatter[r] : r;
            float* Crow = C + (size_t)cr * N + col0 + tx * 4;
            #pragma unroll
            for (int j = 0; j < 4; j++)
                Crow[j] = acc[i][j] + bias[col0 + tx * 4 + j];
        }
    }
}

// ---------------- persistent lattice scan with g-cache ----------------
// 64 CTAs x 512 threads; CTA owns 8 H-columns (j0..j0+7).
//   warps 0-5  : U    dots on h_{t-1}                       -> sh_act
//   warps 6-11 : Uw   g-cache for h_{t-1}                   -> sh_gring
//   warps 12-15: Ua   dots on full c_w  (stage 2)           -> sh_alpha
//   warps 14-15: cp.async prefetch of t+1 operands (double-buffered SMEM)
// Grid sync: all-poll flag barrier (no atomics, MLP polls).
__global__ void __launch_bounds__(NTH, 1) scan_kernel(
    const float* __restrict__ h0, const float* __restrict__ c0,
    const int* __restrict__ word_starts,
    const float* __restrict__ U, const float* __restrict__ Uw,
    const float* __restrict__ Ua, float* __restrict__ out)
{
    const int tid  = threadIdx.x;
    const int wid  = tid >> 5;
    const int lane = tid & 31;
    const int cta  = blockIdx.x;
    const int j0   = cta * CP;

    __shared__ float sh_h[HN];
    __shared__ float sh_cw[WN][HN];
    __shared__ float sh_act[3][CP];
    __shared__ float sh_alpha[WN][CP];
    __shared__ float sh_cwown[WN][CP];
    __shared__ float sh_gring[RING][3][CP];   // Uw^T h_s (own cols), slot s&7
    __shared__ float sh_cring[RING][CP];      // c_s (own cols), slot s&7
    __shared__ __align__(16) float pb_px [2][3][CP];
    __shared__ __align__(16) float pb_pxa[2][CP];
    __shared__ __align__(16) float pb_pxw[2][WN][3][CP];
    __shared__ __align__(16) int   pb_starts[2][WN];
    __shared__ __align__(16) unsigned char pb_mask[2][4];

    // ---- weight columns in registers (row mapping r = lane + 32*m) ----
    float wreg[4][16];     // U (warps 0-5) or Uw (warps 6-11)
    float wua [2][16];     // Ua (warps 12-15)
    #pragma unroll
    for (int k = 0; k < 4; k++)
        #pragma unroll
        for (int m = 0; m < 16; m++) wreg[k][m] = 0.0f;
    #pragma unroll
    for (int k = 0; k < 2; k++)
        #pragma unroll
        for (int m = 0; m < 16; m++) wua[k][m] = 0.0f;

    if (wid < 6) {
        int q = wid >> 1, half = wid & 1;
        const float* base = U + (size_t)(q * 512 + j0 + half * 4);
        #pragma unroll
        for (int m = 0; m < 16; m++) {
            int r = lane + 32 * m;
            #pragma unroll
            for (int k = 0; k < 4; k++) wreg[k][m] = base[(size_t)r * G3H + k];
        }
    } else if (wid < 12) {
        int q = (wid - 6) >> 1, half = (wid - 6) & 1;
        const float* base = Uw + (size_t)(q * 512 + j0 + half * 4);
        #pragma unroll
        for (int m = 0; m < 16; m++) {
            int r = lane + 32 * m;
            #pragma unroll
            for (int k = 0; k < 4; k++) wreg[k][m] = base[(size_t)r * G3H + k];
        }
    } else {
        int p = wid - 12;
        const float* base = Ua + (size_t)(j0 + 2 * p);
        #pragma unroll
        for (int m = 0; m < 16; m++) {
            int r = lane + 32 * m;
            #pragma unroll
            for (int k = 0; k < 2; k++) wua[k][m] = base[(size_t)r * HN + k];
        }
    }

    // c-ring seed: slot (0-1)&7 == 7 holds c0 (for the t=0 no-word branch)
    if (tid < CP) sh_cring[7][tid] = c0[j0 + tid];

    // ---- prefetch issuer (warps 14-15: 64 lanes cover 34 chunk tasks) ----
    auto issue_pf = [&](int tt, int bb) {
        int r = (wid - 14) * 32 + lane;
        if (r < 6) {
            int q = r >> 1, c = r & 1;
            cp16(&pb_px[bb][q][c * 4], &g_px[(size_t)tt * G3H + q * 512 + j0 + c * 4]);
        } else if (r < 8) {
            int c = r - 6;
            cp16(&pb_pxa[bb][c * 4], &g_pxa[(size_t)tt * HN + j0 + c * 4]);
        } else if (r < 32) {
            int i = r - 8;
            int w = i / 6, rem = i % 6, q = rem >> 1, c = rem & 1;
            cp16(&pb_pxw[bb][w][q][c * 4],
                 &g_pxw[((size_t)tt * WN + w) * G3H + q * 512 + j0 + c * 4]);
        } else if (r == 32) {
            cp16(&pb_starts[bb][0], &word_starts[tt * WN]);
        } else if (r == 33) {
            cp4(&pb_mask[bb][0], &g_mask[tt * WN]);
        }
    };

    // prologue: fetch t=0 operands
    if (wid >= 14) {
        issue_pf(0, 0);
        cp_commit();
        cp_waitall();
    }
    __syncthreads();

    int bar_epoch = 0;

    for (int t = 0; t < TN; t++) {
        const int b = t & 1;
        // issue prefetch for t+1 (hidden behind this whole step)
        {
            int tnn = (t + 1 < TN) ? t + 1 : t;
            if (wid >= 14) { issue_pf(tnn, b ^ 1); cp_commit(); }
        }

        const int m0 = pb_mask[b][0], m1 = pb_mask[b][1];
        const int m2 = pb_mask[b][2], m3 = pb_mask[b][3];
        const bool anyw = (m0 | m1 | m2 | m3) != 0;

        // ---- stage h_{t-1} (only cross-CTA state needed) ----
        {
            const float* hp = t ? (out + (size_t)(t - 1) * (2 * HN)) : h0;
            sh_h[tid] = hp[tid];
        }
        __syncthreads();                                          // S1

        // ---- stage 1: U dots (warps 0-5) || g-cache for h_{t-1} (warps 6-11) ----
        if (wid < 6) {
            int q = wid >> 1, half = wid & 1;
            float d[4] = {0.f, 0.f, 0.f, 0.f};
            #pragma unroll
            for (int m = 0; m < 16; m++) {
                float hv = sh_h[lane + 32 * m];
                #pragma unroll
                for (int k = 0; k < 4; k++) d[k] = fmaf(hv, wreg[k][m], d[k]);
            }
            #pragma unroll
            for (int off = 16; off > 0; off >>= 1)
                #pragma unroll
                for (int k = 0; k < 4; k++) d[k] += __shfl_xor_sync(0xffffffffu, d[k], off);
            if (lane == 0) {
                #pragma unroll
                for (int k = 0; k < 4; k++) {
                    float v = pb_px[b][q][half * 4 + k] + d[k];
                    sh_act[q][half * 4 + k] = (q == 2) ? tanh_f(v) : sigm_f(v);
                }
            }
        } else if (wid < 12 && t > 0) {
            int q = (wid - 6) >> 1, half = (wid - 6) & 1;
            float d[4] = {0.f, 0.f, 0.f, 0.f};
            #pragma unroll
            for (int m = 0; m < 16; m++) {
                float hv = sh_h[lane + 32 * m];
                #pragma unroll
                for (int k = 0; k < 4; k++) d[k] = fmaf(hv, wreg[k][m], d[k]);
            }
            #pragma unroll
            for (int off = 16; off > 0; off >>= 1)
                #pragma unroll
                for (int k = 0; k < 4; k++) d[k] += __shfl_xor_sync(0xffffffffu, d[k], off);
            if (lane == 0) {
                int slot = (t - 1) & (RING - 1);
                #pragma unroll
                for (int k = 0; k < 4; k++)
                    sh_gring[slot][q][half * 4 + k] = d[k];
            }
        }
        __syncthreads();                                          // S2

        if (anyw) {
            // ---- c_w from g-cache + c-ring; publish own columns ----
            if (tid < 32) {
                int w = tid >> 3, k = tid & 7;
                int mm = (w == 0) ? m0 : (w == 1) ? m1 : (w == 2) ? m2 : m3;
                if (mm) {
                    int slot = pb_starts[b][w] & (RING - 1);
                    float f  = pb_pxw[b][w][0][k] + sh_gring[slot][0][k];
                    float iw = pb_pxw[b][w][1][k] + sh_gring[slot][1][k];
                    float gw = pb_pxw[b][w][2][k] + sh_gring[slot][2][k];
                    float cs = sh_cring[slot][k];
                    float cw = sigm_f(f) * cs + sigm_f(iw) * tanh_f(gw);
                    sh_cwown[w][k] = cw;
                    g_cw[w * HN + j0 + k] = cw;
                }
            }
            __syncthreads();                                      // S3 (order stores before release)
            bar_epoch++;
            if (tid == 0) gbar(cta, bar_epoch);                   // barrier A
            __syncthreads();                                      // S4

            // ---- stage full c_w ----
            sh_cw[0][tid] = m0 ? g_cw[0 * HN + tid] : 0.0f;
            sh_cw[1][tid] = m1 ? g_cw[1 * HN + tid] : 0.0f;
            sh_cw[2][tid] = m2 ? g_cw[2 * HN + tid] : 0.0f;
            sh_cw[3][tid] = m3 ? g_cw[3 * HN + tid] : 0.0f;
            __syncthreads();                                      // S5

            // ---- stage 2: alpha (warps 12-15) ----
            if (wid >= 12) {
                int p = wid - 12;
                float a2[4][2];
                #pragma unroll
                for (int w = 0; w < 4; w++)
                    #pragma unroll
                    for (int k = 0; k < 2; k++) a2[w][k] = 0.0f;
                #pragma unroll
                for (int w = 0; w < 4; w++) {
                    #pragma unroll
                    for (int m = 0; m < 16; m++) {
                        float cv = sh_cw[w][lane + 32 * m];
                        #pragma unroll
                        for (int k = 0; k < 2; k++) a2[w][k] = fmaf(cv, wua[k][m], a2[w][k]);
                    }
                }
                #pragma unroll
                for (int off = 16; off > 0; off >>= 1)
                    #pragma unroll
                    for (int w = 0; w < 4; w++)
                        #pragma unroll
                        for (int k = 0; k < 2; k++)
                            a2[w][k] += __shfl_xor_sync(0xffffffffu, a2[w][k], off);
                if (lane == 0) {
                    #pragma unroll
                    for (int w = 0; w < 4; w++)
                        #pragma unroll
                        for (int k = 0; k < 2; k++)
                            sh_alpha[w][2 * p + k] = sigm_f(pb_pxa[b][2 * p + k] + a2[w][k]);
                }
            }
            __syncthreads();                                      // S6
        }

        // ---- combine + publish h_t / c_t ----
        if (tid < CP) {
            int k = tid;
            float ig = sh_act[0][k], og = sh_act[1][k], gg = sh_act[2][k];
            float c1;
            if (anyw) {
                float e0  = __expf(ig);
                float den = e0, num = e0 * gg;
                if (m0) { float ea = __expf(sh_alpha[0][k]); den += ea; num = fmaf(ea, sh_cwown[0][k], num); }
                if (m1) { float ea = __expf(sh_alpha[1][k]); den += ea; num = fmaf(ea, sh_cwown[1][k], num); }
                if (m2) { float ea = __expf(sh_alpha[2][k]); den += ea; num = fmaf(ea, sh_cwown[2][k], num); }
                if (m3) { float ea = __expf(sh_alpha[3][k]); den += ea; num = fmaf(ea, sh_cwown[3][k], num); }
                c1 = num / den;
            } else {
                c1 = (1.0f - ig) * sh_cring[(t - 1) & (RING - 1)][k] + ig * gg;
            }
            float h1 = og * tanh_f(c1);
            sh_cring[t & (RING - 1)][k] = c1;
            out[(size_t)t * (2 * HN) + j0 + k]      = h1;
            out[(size_t)t * (2 * HN) + HN + j0 + k] = c1;
        }
        __syncthreads();                                          // S7 (order out stores before release)

        bar_epoch++;
        if (tid == 0) gbar(cta, bar_epoch);                       // barrier B
        if (wid >= 14) cp_waitall();   // prefetch for t+1 has landed
        __syncthreads();                                          // S8
    }
}

// ---------------- launch ----------------
extern "C" void kernel_launch(void* const* d_in, const int* in_sizes, int n_in,
                              void* d_out, int out_size)
{
    const float*         x     = (const float*)d_in[0];
    const int*           wids  = (const int*)d_in[1];
    const int*           wst   = (const int*)d_in[2];
    const unsigned char* wmask = (const unsigned char*)d_in[3];
    const float*         h0    = (const float*)d_in[4];
    const float*         c0    = (const float*)d_in[5];
    const float*         emb   = (const float*)d_in[6];
    const float*         W     = (const float*)d_in[7];
    const float*         U     = (const float*)d_in[8];
    const float*         b     = (const float*)d_in[9];
    const float*         Wa    = (const float*)d_in[10];
    const float*         Ua    = (const float*)d_in[11];
    const float*         ba    = (const float*)d_in[12];
    const float*         Ww    = (const float*)d_in[13];
    const float*         Uw    = (const float*)d_in[14];
    const float*         bw    = (const float*)d_in[15];
    float*               out   = (float*)d_out;

    prep_kernel<<<1, 256>>>(wmask);
    build_active_kernel<<<(TN * WN + 255) / 256, 256>>>(wids);

    // px = x @ W + b          [4096 x 1536], K=128
    sgemm_kernel<<<dim3(G3H / 64, TN / 64), 256>>>(x, W, b, TN, G3H, DN, 0, 0);
    // pxa = x @ Wa + ba       [4096 x 512], K=128
    sgemm_kernel<<<dim3(HN / 64, TN / 64), 256>>>(x, Wa, ba, TN, HN, DN, 0, 1);
    // pxw = emb[gather] @ Ww + bw, scattered rows, K=256
    sgemm_kernel<<<dim3(G3H / 64, (TN * WN) / 64), 256>>>(emb, Ww, bw, TN * WN, G3H, EN, 1, 2);

    scan_kernel<<<NC, NTH>>>(h0, c0, wst, U, Uw, Ua, out);
}

// round 13
// speedup vs baseline: 2.2003x; 2.2003x over previous
#include <cuda_runtime.h>
#include <cuda_bf16.h>
#include <math.h>

// ---------------- problem constants ----------------
#define TN   4096
#define DN   128
#define HN   512
#define EN   256
#define WN   4
#define G3H  1536

// scan config
#define NC   64       // persistent CTAs
#define NTH  512      // 16 warps
#define CP   8        // H-columns owned per CTA (NC*CP = 512)
#define RING 8        // lookback ring (word length <= 6 -> s >= t-5)

// ---------------- device scratch (static; no cudaMalloc) ----------------
__device__ float g_px [(size_t)TN * G3H];         // x@W + b
__device__ float g_pxa[(size_t)TN * HN];          // x@Wa + ba
__device__ float g_pxw[(size_t)TN * WN * G3H];    // emb[wid]@Ww + bw (active only)
__device__ float g_cw [2 * WN * HN];              // c_w exchange, double-buffered by step parity
__device__ int   g_barA;                          // barrier-A counter (cw exchange)
__device__ int   g_barB;                          // barrier-B counter (h/c publish)
__device__ int   g_nact;                          // number of active (t,w)
__device__ int   g_gather [TN * WN];              // active -> word id (emb row)
__device__ int   g_scatter[TN * WN];              // active -> flat (t*WN+w)
__device__ unsigned char g_mask[TN * WN];         // decoded bool mask

// ---------------- helpers ----------------
__device__ __forceinline__ int ld_acq(const int* p) {
    int v;
    asm volatile("ld.global.acquire.gpu.b32 %0, [%1];" : "=r"(v) : "l"(p) : "memory");
    return v;
}
__device__ __forceinline__ void red_rel_add1(int* p) {
    asm volatile("red.release.gpu.global.add.s32 [%0], 1;" :: "l"(p) : "memory");
}
__device__ __forceinline__ void cp16(void* dst, const void* src) {
    unsigned s = (unsigned)__cvta_generic_to_shared(dst);
    asm volatile("cp.async.ca.shared.global [%0], [%1], 16;" :: "r"(s), "l"(src));
}
__device__ __forceinline__ void cp4(void* dst, const void* src) {
    unsigned s = (unsigned)__cvta_generic_to_shared(dst);
    asm volatile("cp.async.ca.shared.global [%0], [%1], 4;" :: "r"(s), "l"(src));
}
__device__ __forceinline__ void cp_commit() { asm volatile("cp.async.commit_group;"); }
__device__ __forceinline__ void cp_waitall() { asm volatile("cp.async.wait_group 0;"); }

__device__ __forceinline__ float sigm_f(float v) { return 1.0f / (1.0f + __expf(-v)); }
__device__ __forceinline__ float tanh_f(float v) {
    v = fminf(fmaxf(v, -10.0f), 10.0f);
    float e = __expf(-2.0f * v);
    return (1.0f - e) / (1.0f + e);
}

// R7-proven spin: acquire poll throttled by short sleep
__device__ __forceinline__ void spin_until(const int* p, int tgt) {
    while (ld_acq(p) < tgt) { __nanosleep(32); }
}

// ---------------- prep: zero counters + decode mask dtype ----------------
__global__ void prep_kernel(const unsigned char* __restrict__ raw) {
    __shared__ int nz[4];
    int tid = threadIdx.x;
    if (tid == 0) { g_barA = 0; g_barB = 0; g_nact = 0; }
    if (tid < 4) nz[tid] = 0;
    __syncthreads();
    for (int i = tid; i < TN * WN; i += blockDim.x)
        if (raw[i]) atomicOr(&nz[i & 3], 1);
    __syncthreads();
    int mode;
    if (nz[0]) mode = (nz[1] | nz[2] | nz[3]) ? 0 : 1;   // 0=u8, 1=i32
    else       mode = (nz[2] | nz[3]) ? 2 : 0;           // 2=f32
    for (int i = tid; i < TN * WN; i += blockDim.x) {
        unsigned char m;
        if (mode == 0)      m = (raw[i] != 0);
        else if (mode == 1) m = (((const int*)raw)[i] != 0);
        else                m = (((const float*)raw)[i] != 0.0f);
        g_mask[i] = m;
    }
}

// ---------------- build compact active-word list ----------------
__global__ void build_active_kernel(const int* __restrict__ word_ids) {
    int i = blockIdx.x * blockDim.x + threadIdx.x;
    if (i < TN * WN && g_mask[i]) {
        int pos = atomicAdd(&g_nact, 1);
        g_gather[pos]  = word_ids[i];
        g_scatter[pos] = i;
    }
}

// ---------------- fp32 SGEMM: C = (gather?)A @ B + bias ----------------
__global__ void __launch_bounds__(256) sgemm_kernel(
    const float* __restrict__ A, const float* __restrict__ B,
    const float* __restrict__ bias,
    int M, int N, int K, int use_gather, int dst_sel)
{
    __shared__ float As[16][68];
    __shared__ float Bs[16][68];

    float* C = (dst_sel == 0) ? g_px : (dst_sel == 1) ? g_pxa : g_pxw;
    int Meff = use_gather ? g_nact : M;
    int row0 = blockIdx.y * 64;
    int col0 = blockIdx.x * 64;
    if (row0 >= Meff) return;

    int tid = threadIdx.x;
    int tx = tid & 15, ty = tid >> 4;

    int arow_l = tid >> 2;
    int ak0    = (tid & 3) * 4;
    int arow_g = row0 + arow_l;
    bool a_ok  = (arow_g < Meff);
    const float* Arow = A;
    if (a_ok) {
        int r = use_gather ? g_gather[arow_g] : arow_g;
        Arow = A + (size_t)r * K;
    }
    int bk  = tid >> 4;
    int bc0 = (tid & 15) * 4;

    float acc[4][4];
    #pragma unroll
    for (int i = 0; i < 4; i++)
        #pragma unroll
        for (int j = 0; j < 4; j++) acc[i][j] = 0.0f;

    for (int k0 = 0; k0 < K; k0 += 16) {
        float4 av = make_float4(0.f, 0.f, 0.f, 0.f);
        if (a_ok) av = *reinterpret_cast<const float4*>(Arow + k0 + ak0);
        As[ak0 + 0][arow_l] = av.x;
        As[ak0 + 1][arow_l] = av.y;
        As[ak0 + 2][arow_l] = av.z;
        As[ak0 + 3][arow_l] = av.w;
        float4 bv = *reinterpret_cast<const float4*>(B + (size_t)(k0 + bk) * N + col0 + bc0);
        *reinterpret_cast<float4*>(&Bs[bk][bc0]) = bv;
        __syncthreads();
        #pragma unroll
        for (int kk = 0; kk < 16; kk++) {
            float4 a4 = *reinterpret_cast<const float4*>(&As[kk][ty * 4]);
            float4 b4 = *reinterpret_cast<const float4*>(&Bs[kk][tx * 4]);
            float aa[4] = {a4.x, a4.y, a4.z, a4.w};
            float bb[4] = {b4.x, b4.y, b4.z, b4.w};
            #pragma unroll
            for (int i = 0; i < 4; i++)
                #pragma unroll
                for (int j = 0; j < 4; j++)
                    acc[i][j] = fmaf(aa[i], bb[j], acc[i][j]);
        }
        __syncthreads();
    }
    #pragma unroll
    for (int i = 0; i < 4; i++) {
        int r = row0 + ty * 4 + i;
        if (r < Meff) {
            int cr = use_gather ? g_scatter[r] : r;
            float* Crow = C + (size_t)cr * N + col0 + tx * 4;
            #pragma unroll
            for (int j = 0; j < 4; j++)
                Crow[j] = acc[i][j] + bias[col0 + tx * 4 + j];
        }
    }
}

// ---------------- persistent lattice scan: g-cache + early-cw barrier hiding ----
// 64 CTAs x 512 threads; CTA owns 8 H-columns (j0..j0+7).
//   warps 0-5  : U    dots on h_{t-1}                       -> sh_act
//   warps 6-11 : Uw   g-cache for h_{t-1}                   -> sh_gring
//   warps 12-15: Ua   dots on full c_w  (stage 2)           -> sh_alpha
//   warps 14-15: cp.async prefetch of t+1 operands (double-buffered SMEM)
// Barrier A (cw) hidden under stage 1 whenever no active word of the next
// step starts at t (length-2): its cw is computed from local rings at the
// tail of step t and published early, so all CTAs arrive at A a phase ahead.
// Separate counters g_barA/g_barB keep early A-arrivals from corrupting B.
__global__ void __launch_bounds__(NTH, 1) scan_kernel(
    const float* __restrict__ h0, const float* __restrict__ c0,
    const int* __restrict__ word_starts,
    const float* __restrict__ U, const float* __restrict__ Uw,
    const float* __restrict__ Ua, float* __restrict__ out)
{
    const int tid  = threadIdx.x;
    const int wid  = tid >> 5;
    const int lane = tid & 31;
    const int cta  = blockIdx.x;
    const int j0   = cta * CP;

    __shared__ float sh_h[HN];
    __shared__ float sh_cw[WN][HN];
    __shared__ float sh_act[3][CP];
    __shared__ float sh_alpha[WN][CP];
    __shared__ float sh_cwown[WN][CP];
    __shared__ float sh_gring[RING][3][CP];   // Uw^T h_s (own cols), slot s&7
    __shared__ float sh_cring[RING][CP];      // c_s (own cols), slot s&7
    __shared__ __align__(16) float pb_px [2][3][CP];
    __shared__ __align__(16) float pb_pxa[2][CP];
    __shared__ __align__(16) float pb_pxw[2][WN][3][CP];
    __shared__ __align__(16) int   pb_starts[2][WN];
    __shared__ __align__(16) unsigned char pb_mask[2][4];

    // ---- weight columns in registers (row mapping r = lane + 32*m) ----
    float wreg[4][16];     // U (warps 0-5) or Uw (warps 6-11)
    float wua [2][16];     // Ua (warps 12-15)
    #pragma unroll
    for (int k = 0; k < 4; k++)
        #pragma unroll
        for (int m = 0; m < 16; m++) wreg[k][m] = 0.0f;
    #pragma unroll
    for (int k = 0; k < 2; k++)
        #pragma unroll
        for (int m = 0; m < 16; m++) wua[k][m] = 0.0f;

    if (wid < 6) {
        int q = wid >> 1, half = wid & 1;
        const float* base = U + (size_t)(q * 512 + j0 + half * 4);
        #pragma unroll
        for (int m = 0; m < 16; m++) {
            int r = lane + 32 * m;
            #pragma unroll
            for (int k = 0; k < 4; k++) wreg[k][m] = base[(size_t)r * G3H + k];
        }
    } else if (wid < 12) {
        int q = (wid - 6) >> 1, half = (wid - 6) & 1;
        const float* base = Uw + (size_t)(q * 512 + j0 + half * 4);
        #pragma unroll
        for (int m = 0; m < 16; m++) {
            int r = lane + 32 * m;
            #pragma unroll
            for (int k = 0; k < 4; k++) wreg[k][m] = base[(size_t)r * G3H + k];
        }
    } else {
        int p = wid - 12;
        const float* base = Ua + (size_t)(j0 + 2 * p);
        #pragma unroll
        for (int m = 0; m < 16; m++) {
            int r = lane + 32 * m;
            #pragma unroll
            for (int k = 0; k < 2; k++) wua[k][m] = base[(size_t)r * HN + k];
        }
    }

    // c-ring seed: slot (0-1)&7 == 7 holds c0 (for the t=0 no-word branch)
    if (tid < CP) sh_cring[7][tid] = c0[j0 + tid];

    // ---- prefetch issuer (warps 14-15: 64 lanes cover 34 chunk tasks) ----
    auto issue_pf = [&](int tt, int bb) {
        int r = (wid - 14) * 32 + lane;
        if (r < 6) {
            int q = r >> 1, c = r & 1;
            cp16(&pb_px[bb][q][c * 4], &g_px[(size_t)tt * G3H + q * 512 + j0 + c * 4]);
        } else if (r < 8) {
            int c = r - 6;
            cp16(&pb_pxa[bb][c * 4], &g_pxa[(size_t)tt * HN + j0 + c * 4]);
        } else if (r < 32) {
            int i = r - 8;
            int w = i / 6, rem = i % 6, q = rem >> 1, c = rem & 1;
            cp16(&pb_pxw[bb][w][q][c * 4],
                 &g_pxw[((size_t)tt * WN + w) * G3H + q * 512 + j0 + c * 4]);
        } else if (r == 32) {
            cp16(&pb_starts[bb][0], &word_starts[tt * WN]);
        } else if (r == 33) {
            cp4(&pb_mask[bb][0], &g_mask[tt * WN]);
        }
    };

    // cw compute + publish (own columns) for the step whose operands live in
    // pb buffer bb; writes sh_cwown and g_cw[buf]. tid<32 only.
    auto compute_cw = [&](int a0, int a1, int a2, int a3, int bb, int buf) {
        if (tid < 32) {
            int w = tid >> 3, k = tid & 7;
            int mm = (w == 0) ? a0 : (w == 1) ? a1 : (w == 2) ? a2 : a3;
            if (mm) {
                int slot = pb_starts[bb][w] & (RING - 1);
                float f  = pb_pxw[bb][w][0][k] + sh_gring[slot][0][k];
                float iw = pb_pxw[bb][w][1][k] + sh_gring[slot][1][k];
                float gw = pb_pxw[bb][w][2][k] + sh_gring[slot][2][k];
                float cs = sh_cring[slot][k];
                float cw = sigm_f(f) * cs + sigm_f(iw) * tanh_f(gw);
                sh_cwown[w][k] = cw;
                g_cw[buf * (WN * HN) + w * HN + j0 + k] = cw;
            }
        }
    };

    // prologue: fetch t=0 operands
    if (wid >= 14) {
        issue_pf(0, 0);
        cp_commit();
        cp_waitall();
    }
    __syncthreads();

    int nA = 0, nB = 0;
    bool early_done = false;
    // guard: if t=0 had active words (reference guarantees not), count its A-barrier
    if (pb_mask[0][0] | pb_mask[0][1] | pb_mask[0][2] | pb_mask[0][3]) nA++;

    for (int t = 0; t < TN; t++) {
        const int b = t & 1;
        // issue prefetch for t+1 (hidden behind this whole step)
        {
            int tnn = (t + 1 < TN) ? t + 1 : t;
            if (wid >= 14) { issue_pf(tnn, b ^ 1); cp_commit(); }
        }

        const int m0 = pb_mask[b][0], m1 = pb_mask[b][1];
        const int m2 = pb_mask[b][2], m3 = pb_mask[b][3];
        const bool anyw = (m0 | m1 | m2 | m3) != 0;

        // ---- stage h_{t-1} (L2, bypass L1 — remote SMs wrote it) ----
        {
            const float* hp = t ? (out + (size_t)(t - 1) * (2 * HN)) : h0;
            sh_h[tid] = __ldcg(hp + tid);
        }
        __syncthreads();                                          // S1

        // ---- stage 1: U dots (warps 0-5) || g-cache for h_{t-1} (warps 6-11) ----
        if (wid < 6) {
            int q = wid >> 1, half = wid & 1;
            float d[4] = {0.f, 0.f, 0.f, 0.f};
            #pragma unroll
            for (int m = 0; m < 16; m++) {
                float hv = sh_h[lane + 32 * m];
                #pragma unroll
                for (int k = 0; k < 4; k++) d[k] = fmaf(hv, wreg[k][m], d[k]);
            }
            #pragma unroll
            for (int off = 16; off > 0; off >>= 1)
                #pragma unroll
                for (int k = 0; k < 4; k++) d[k] += __shfl_xor_sync(0xffffffffu, d[k], off);
            if (lane == 0) {
                #pragma unroll
                for (int k = 0; k < 4; k++) {
                    float v = pb_px[b][q][half * 4 + k] + d[k];
                    sh_act[q][half * 4 + k] = (q == 2) ? tanh_f(v) : sigm_f(v);
                }
            }
        } else if (wid < 12 && t > 0) {
            int q = (wid - 6) >> 1, half = (wid - 6) & 1;
            float d[4] = {0.f, 0.f, 0.f, 0.f};
            #pragma unroll
            for (int m = 0; m < 16; m++) {
                float hv = sh_h[lane + 32 * m];
                #pragma unroll
                for (int k = 0; k < 4; k++) d[k] = fmaf(hv, wreg[k][m], d[k]);
            }
            #pragma unroll
            for (int off = 16; off > 0; off >>= 1)
                #pragma unroll
                for (int k = 0; k < 4; k++) d[k] += __shfl_xor_sync(0xffffffffu, d[k], off);
            if (lane == 0) {
                int slot = (t - 1) & (RING - 1);
                #pragma unroll
                for (int k = 0; k < 4; k++)
                    sh_gring[slot][q][half * 4 + k] = d[k];
            }
        }
        __syncthreads();                                          // S2

        if (anyw) {
            if (!early_done) {
                // deferred path: a length-2 word needed gring[t-1] (just computed)
                compute_cw(m0, m1, m2, m3, b, b);
                __syncthreads();                                  // S3
                if (tid == 0) red_rel_add1(&g_barA);
            }
            if (tid == 0) spin_until(&g_barA, NC * nA);           // barrier A (often pre-completed)
            __syncthreads();                                      // S4

            // ---- stage full c_w (L2, bypass L1) ----
            {
                const float* cwb = &g_cw[b * (WN * HN)];
                sh_cw[0][tid] = m0 ? __ldcg(cwb + 0 * HN + tid) : 0.0f;
                sh_cw[1][tid] = m1 ? __ldcg(cwb + 1 * HN + tid) : 0.0f;
                sh_cw[2][tid] = m2 ? __ldcg(cwb + 2 * HN + tid) : 0.0f;
                sh_cw[3][tid] = m3 ? __ldcg(cwb + 3 * HN + tid) : 0.0f;
            }
            __syncthreads();                                      // S5

            // ---- stage 2: alpha (warps 12-15) ----
            if (wid >= 12) {
                int p = wid - 12;
                float a2[4][2];
                #pragma unroll
                for (int w = 0; w < 4; w++)
                    #pragma unroll
                    for (int k = 0; k < 2; k++) a2[w][k] = 0.0f;
                #pragma unroll
                for (int w = 0; w < 4; w++) {
                    #pragma unroll
                    for (int m = 0; m < 16; m++) {
                        float cv = sh_cw[w][lane + 32 * m];
                        #pragma unroll
                        for (int k = 0; k < 2; k++) a2[w][k] = fmaf(cv, wua[k][m], a2[w][k]);
                    }
                }
                #pragma unroll
                for (int off = 16; off > 0; off >>= 1)
                    #pragma unroll
                    for (int w = 0; w < 4; w++)
                        #pragma unroll
                        for (int k = 0; k < 2; k++)
                            a2[w][k] += __shfl_xor_sync(0xffffffffu, a2[w][k], off);
                if (lane == 0) {
                    #pragma unroll
                    for (int w = 0; w < 4; w++)
                        #pragma unroll
                        for (int k = 0; k < 2; k++)
                            sh_alpha[w][2 * p + k] = sigm_f(pb_pxa[b][2 * p + k] + a2[w][k]);
                }
            }
            __syncthreads();                                      // S6
        }

        // ---- combine + publish h_t / c_t ----
        if (tid < CP) {
            int k = tid;
            float ig = sh_act[0][k], og = sh_act[1][k], gg = sh_act[2][k];
            float c1;
            if (anyw) {
                float e0  = __expf(ig);
                float den = e0, num = e0 * gg;
                if (m0) { float ea = __expf(sh_alpha[0][k]); den += ea; num = fmaf(ea, sh_cwown[0][k], num); }
                if (m1) { float ea = __expf(sh_alpha[1][k]); den += ea; num = fmaf(ea, sh_cwown[1][k], num); }
                if (m2) { float ea = __expf(sh_alpha[2][k]); den += ea; num = fmaf(ea, sh_cwown[2][k], num); }
                if (m3) { float ea = __expf(sh_alpha[3][k]); den += ea; num = fmaf(ea, sh_cwown[3][k], num); }
                c1 = num / den;
            } else {
                c1 = (1.0f - ig) * sh_cring[(t - 1) & (RING - 1)][k] + ig * gg;
            }
            float h1 = og * tanh_f(c1);
            sh_cring[t & (RING - 1)][k] = c1;
            out[(size_t)t * (2 * HN) + j0 + k]      = h1;
            out[(size_t)t * (2 * HN) + HN + j0 + k] = c1;
        }
        __syncthreads();                                          // S7 (order out stores before release)

        nB++;
        if (tid == 0) red_rel_add1(&g_barB);                      // arrive B(t) (wait deferred)

        if (wid >= 14) cp_waitall();                              // t+1 operands landed
        __syncthreads();                                          // S8

        // ---- tail: early cw for step t+1 if no active word starts at t ----
        early_done = false;
        if (t + 1 < TN) {
            const int bn = b ^ 1;
            const int n0 = pb_mask[bn][0], n1 = pb_mask[bn][1];
            const int n2 = pb_mask[bn][2], n3 = pb_mask[bn][3];
            if (n0 | n1 | n2 | n3) {
                nA++;
                bool early = true;
                if (n0 && pb_starts[bn][0] > t - 1) early = false;
                if (n1 && pb_starts[bn][1] > t - 1) early = false;
                if (n2 && pb_starts[bn][2] > t - 1) early = false;
                if (n3 && pb_starts[bn][3] > t - 1) early = false;
                if (early) {
                    compute_cw(n0, n1, n2, n3, bn, bn);
                    __syncthreads();                              // S9
                    if (tid == 0) red_rel_add1(&g_barA);          // early arrival at A(t+1)
                    early_done = true;
                }
            }
        }

        if (tid == 0) spin_until(&g_barB, NC * nB);               // barrier B wait
        __syncthreads();                                          // S10
    }
}

// ---------------- launch ----------------
extern "C" void kernel_launch(void* const* d_in, const int* in_sizes, int n_in,
                              void* d_out, int out_size)
{
    const float*         x     = (const float*)d_in[0];
    const int*           wids  = (const int*)d_in[1];
    const int*           wst   = (const int*)d_in[2];
    const unsigned char* wmask = (const unsigned char*)d_in[3];
    const float*         h0    = (const float*)d_in[4];
    const float*         c0    = (const float*)d_in[5];
    const float*         emb   = (const float*)d_in[6];
    const float*         W     = (const float*)d_in[7];
    const float*         U     = (const float*)d_in[8];
    const float*         b     = (const float*)d_in[9];
    const float*         Wa    = (const float*)d_in[10];
    const float*         Ua    = (const float*)d_in[11];
    const float*         ba    = (const float*)d_in[12];
    const float*         Ww    = (const float*)d_in[13];
    const float*         Uw    = (const float*)d_in[14];
    const float*         bw    = (const float*)d_in[15];
    float*               out   = (float*)d_out;

    prep_kernel<<<1, 256>>>(wmask);
    build_active_kernel<<<(TN * WN + 255) / 256, 256>>>(wids);

    // px = x @ W + b          [4096 x 1536], K=128
    sgemm_kernel<<<dim3(G3H / 64, TN / 64), 256>>>(x, W, b, TN, G3H, DN, 0, 0);
    // pxa = x @ Wa + ba       [4096 x 512], K=128
    sgemm_kernel<<<dim3(HN / 64, TN / 64), 256>>>(x, Wa, ba, TN, HN, DN, 0, 1);
    // pxw = emb[gather] @ Ww + bw, scattered rows, K=256
    sgemm_kernel<<<dim3(G3H / 64, (TN * WN) / 64), 256>>>(emb, Ww, bw, TN * WN, G3H, EN, 1, 2);

    scan_kernel<<<NC, NTH>>>(h0, c0, wst, U, Uw, Ua, out);
}

// round 14
// speedup vs baseline: 2.7163x; 1.2345x over previous
#include <cuda_runtime.h>
#include <cuda_bf16.h>
#include <math.h>

// ---------------- problem constants ----------------
#define TN   4096
#define DN   128
#define HN   512
#define EN   256
#define WN   4
#define G3H  1536

// scan config
#define NC   64       // persistent CTAs
#define NTH  512      // 16 warps
#define CP   8        // H-columns owned per CTA (NC*CP = 512)
#define RING 8        // lookback ring (word length <= 6 -> s >= t-5)

// ---------------- device scratch (static; no cudaMalloc) ----------------
__device__ float g_px [(size_t)TN * G3H];         // x@W + b
__device__ float g_pxa[(size_t)TN * HN];          // x@Wa + ba
__device__ float g_pxw[(size_t)TN * WN * G3H];    // emb[wid]@Ww + bw (active only)
__device__ __align__(16) float g_cw [2 * WN * HN];// c_w exchange, double-buffered by parity
__device__ int   g_barA;                          // barrier-A counter (cw exchange)
__device__ int   g_barB;                          // barrier-B counter (h/c publish)
__device__ int   g_nact;                          // number of active (t,w)
__device__ int   g_gather [TN * WN];              // active -> word id (emb row)
__device__ int   g_scatter[TN * WN];              // active -> flat (t*WN+w)
__device__ unsigned char g_mask[TN * WN];         // decoded bool mask

// ---------------- helpers ----------------
__device__ __forceinline__ int ld_acq(const int* p) {
    int v;
    asm volatile("ld.global.acquire.gpu.b32 %0, [%1];" : "=r"(v) : "l"(p) : "memory");
    return v;
}
__device__ __forceinline__ void red_rel_add1(int* p) {
    asm volatile("red.release.gpu.global.add.s32 [%0], 1;" :: "l"(p) : "memory");
}
__device__ __forceinline__ void cp16(void* dst, const void* src) {
    unsigned s = (unsigned)__cvta_generic_to_shared(dst);
    asm volatile("cp.async.ca.shared.global [%0], [%1], 16;" :: "r"(s), "l"(src));
}
__device__ __forceinline__ void cp4(void* dst, const void* src) {
    unsigned s = (unsigned)__cvta_generic_to_shared(dst);
    asm volatile("cp.async.ca.shared.global [%0], [%1], 4;" :: "r"(s), "l"(src));
}
__device__ __forceinline__ void cp_commit() { asm volatile("cp.async.commit_group;"); }
__device__ __forceinline__ void cp_waitall() { asm volatile("cp.async.wait_group 0;"); }

__device__ __forceinline__ void barX() {   // warps 0-11
    asm volatile("bar.sync 1, 384;" ::: "memory");
}
__device__ __forceinline__ void barY() {   // warps 12-15
    asm volatile("bar.sync 2, 128;" ::: "memory");
}

__device__ __forceinline__ float sigm_f(float v) { return 1.0f / (1.0f + __expf(-v)); }
__device__ __forceinline__ float tanh_f(float v) {
    v = fminf(fmaxf(v, -10.0f), 10.0f);
    float e = __expf(-2.0f * v);
    return (1.0f - e) / (1.0f + e);
}

// R7-proven spin: acquire poll throttled by short sleep
__device__ __forceinline__ void spin_until(const int* p, int tgt) {
    while (ld_acq(p) < tgt) { __nanosleep(32); }
}

// ---------------- prep: zero counters + decode mask dtype ----------------
__global__ void prep_kernel(const unsigned char* __restrict__ raw) {
    __shared__ int nz[4];
    int tid = threadIdx.x;
    if (tid == 0) { g_barA = 0; g_barB = 0; g_nact = 0; }
    if (tid < 4) nz[tid] = 0;
    __syncthreads();
    for (int i = tid; i < TN * WN; i += blockDim.x)
        if (raw[i]) atomicOr(&nz[i & 3], 1);
    __syncthreads();
    int mode;
    if (nz[0]) mode = (nz[1] | nz[2] | nz[3]) ? 0 : 1;   // 0=u8, 1=i32
    else       mode = (nz[2] | nz[3]) ? 2 : 0;           // 2=f32
    for (int i = tid; i < TN * WN; i += blockDim.x) {
        unsigned char m;
        if (mode == 0)      m = (raw[i] != 0);
        else if (mode == 1) m = (((const int*)raw)[i] != 0);
        else                m = (((const float*)raw)[i] != 0.0f);
        g_mask[i] = m;
    }
}

// ---------------- build compact active-word list ----------------
__global__ void build_active_kernel(const int* __restrict__ word_ids) {
    int i = blockIdx.x * blockDim.x + threadIdx.x;
    if (i < TN * WN && g_mask[i]) {
        int pos = atomicAdd(&g_nact, 1);
        g_gather[pos]  = word_ids[i];
        g_scatter[pos] = i;
    }
}

// ---------------- fp32 SGEMM: C = (gather?)A @ B + bias ----------------
__global__ void __launch_bounds__(256) sgemm_kernel(
    const float* __restrict__ A, const float* __restrict__ B,
    const float* __restrict__ bias,
    int M, int N, int K, int use_gather, int dst_sel)
{
    __shared__ float As[16][68];
    __shared__ float Bs[16][68];

    float* C = (dst_sel == 0) ? g_px : (dst_sel == 1) ? g_pxa : g_pxw;
    int Meff = use_gather ? g_nact : M;
    int row0 = blockIdx.y * 64;
    int col0 = blockIdx.x * 64;
    if (row0 >= Meff) return;

    int tid = threadIdx.x;
    int tx = tid & 15, ty = tid >> 4;

    int arow_l = tid >> 2;
    int ak0    = (tid & 3) * 4;
    int arow_g = row0 + arow_l;
    bool a_ok  = (arow_g < Meff);
    const float* Arow = A;
    if (a_ok) {
        int r = use_gather ? g_gather[arow_g] : arow_g;
        Arow = A + (size_t)r * K;
    }
    int bk  = tid >> 4;
    int bc0 = (tid & 15) * 4;

    float acc[4][4];
    #pragma unroll
    for (int i = 0; i < 4; i++)
        #pragma unroll
        for (int j = 0; j < 4; j++) acc[i][j] = 0.0f;

    for (int k0 = 0; k0 < K; k0 += 16) {
        float4 av = make_float4(0.f, 0.f, 0.f, 0.f);
        if (a_ok) av = *reinterpret_cast<const float4*>(Arow + k0 + ak0);
        As[ak0 + 0][arow_l] = av.x;
        As[ak0 + 1][arow_l] = av.y;
        As[ak0 + 2][arow_l] = av.z;
        As[ak0 + 3][arow_l] = av.w;
        float4 bv = *reinterpret_cast<const float4*>(B + (size_t)(k0 + bk) * N + col0 + bc0);
        *reinterpret_cast<float4*>(&Bs[bk][bc0]) = bv;
        __syncthreads();
        #pragma unroll
        for (int kk = 0; kk < 16; kk++) {
            float4 a4 = *reinterpret_cast<const float4*>(&As[kk][ty * 4]);
            float4 b4 = *reinterpret_cast<const float4*>(&Bs[kk][tx * 4]);
            float aa[4] = {a4.x, a4.y, a4.z, a4.w};
            float bb[4] = {b4.x, b4.y, b4.z, b4.w};
            #pragma unroll
            for (int i = 0; i < 4; i++)
                #pragma unroll
                for (int j = 0; j < 4; j++)
                    acc[i][j] = fmaf(aa[i], bb[j], acc[i][j]);
        }
        __syncthreads();
    }
    #pragma unroll
    for (int i = 0; i < 4; i++) {
        int r = row0 + ty * 4 + i;
        if (r < Meff) {
            int cr = use_gather ? g_scatter[r] : r;
            float* Crow = C + (size_t)cr * N + col0 + tx * 4;
            #pragma unroll
            for (int j = 0; j < 4; j++)
                Crow[j] = acc[i][j] + bias[col0 + tx * 4 + j];
        }
    }
}

// ---------------- persistent lattice scan: warp-specialized overlap ----------
// 64 CTAs x 512 threads; CTA owns 8 H-columns (j0..j0+7).
// Group X (warps 0-11): h stage + U dots (0-5) + Uw g-cache (6-11); named bar 1.
// Group Y (warps 12-15): spin barrier A, stage c_w, Ua dots -> alpha; named bar 2.
//   Y runs CONCURRENTLY with X's stage 1 (A usually pre-completed by the
//   previous step's tail publish). One full __syncthreads joins them before
//   combine. Warps 14-15 also issue cp.async prefetch of t+1 operands.
// Barrier A hidden by tail publish when no next-step word starts at t (len-2);
// barrier B arrive moved to right after combine's stores (warp-0 syncwarp).
__global__ void __launch_bounds__(NTH, 1) scan_kernel(
    const float* __restrict__ h0, const float* __restrict__ c0,
    const int* __restrict__ word_starts,
    const float* __restrict__ U, const float* __restrict__ Uw,
    const float* __restrict__ Ua, float* __restrict__ out)
{
    const int tid  = threadIdx.x;
    const int wid  = tid >> 5;
    const int lane = tid & 31;
    const int cta  = blockIdx.x;
    const int j0   = cta * CP;

    __shared__ __align__(16) float sh_h[HN];
    __shared__ __align__(16) float sh_cw[WN][HN];
    __shared__ float sh_act[3][CP];
    __shared__ float sh_alpha[WN][CP];
    __shared__ float sh_cwown[WN][CP];
    __shared__ float sh_gring[RING][3][CP];   // Uw^T h_s (own cols), slot s&7
    __shared__ float sh_cring[RING][CP];      // c_s (own cols), slot s&7
    __shared__ __align__(16) float pb_px [2][3][CP];
    __shared__ __align__(16) float pb_pxa[2][CP];
    __shared__ __align__(16) float pb_pxw[2][WN][3][CP];
    __shared__ __align__(16) int   pb_starts[2][WN];
    __shared__ __align__(16) unsigned char pb_mask[2][4];

    // ---- weight columns in registers (row mapping r = lane + 32*m) ----
    float wreg[4][16];     // U (warps 0-5) or Uw (warps 6-11)
    float wua [2][16];     // Ua (warps 12-15)
    #pragma unroll
    for (int k = 0; k < 4; k++)
        #pragma unroll
        for (int m = 0; m < 16; m++) wreg[k][m] = 0.0f;
    #pragma unroll
    for (int k = 0; k < 2; k++)
        #pragma unroll
        for (int m = 0; m < 16; m++) wua[k][m] = 0.0f;

    if (wid < 6) {
        int q = wid >> 1, half = wid & 1;
        const float* base = U + (size_t)(q * 512 + j0 + half * 4);
        #pragma unroll
        for (int m = 0; m < 16; m++) {
            int r = lane + 32 * m;
            #pragma unroll
            for (int k = 0; k < 4; k++) wreg[k][m] = base[(size_t)r * G3H + k];
        }
    } else if (wid < 12) {
        int q = (wid - 6) >> 1, half = (wid - 6) & 1;
        const float* base = Uw + (size_t)(q * 512 + j0 + half * 4);
        #pragma unroll
        for (int m = 0; m < 16; m++) {
            int r = lane + 32 * m;
            #pragma unroll
            for (int k = 0; k < 4; k++) wreg[k][m] = base[(size_t)r * G3H + k];
        }
    } else {
        int p = wid - 12;
        const float* base = Ua + (size_t)(j0 + 2 * p);
        #pragma unroll
        for (int m = 0; m < 16; m++) {
            int r = lane + 32 * m;
            #pragma unroll
            for (int k = 0; k < 2; k++) wua[k][m] = base[(size_t)r * HN + k];
        }
    }

    // c-ring seed: slot (0-1)&7 == 7 holds c0 (for the t=0 no-word branch)
    if (tid < CP) sh_cring[7][tid] = c0[j0 + tid];

    // ---- prefetch issuer (warps 14-15: 64 lanes cover 34 chunk tasks) ----
    auto issue_pf = [&](int tt, int bb) {
        int r = (wid - 14) * 32 + lane;
        if (r < 6) {
            int q = r >> 1, c = r & 1;
            cp16(&pb_px[bb][q][c * 4], &g_px[(size_t)tt * G3H + q * 512 + j0 + c * 4]);
        } else if (r < 8) {
            int c = r - 6;
            cp16(&pb_pxa[bb][c * 4], &g_pxa[(size_t)tt * HN + j0 + c * 4]);
        } else if (r < 32) {
            int i = r - 8;
            int w = i / 6, rem = i % 6, q = rem >> 1, c = rem & 1;
            cp16(&pb_pxw[bb][w][q][c * 4],
                 &g_pxw[((size_t)tt * WN + w) * G3H + q * 512 + j0 + c * 4]);
        } else if (r == 32) {
            cp16(&pb_starts[bb][0], &word_starts[tt * WN]);
        } else if (r == 33) {
            cp4(&pb_mask[bb][0], &g_mask[tt * WN]);
        }
    };

    // cw compute + publish (own columns). Executed by warp 0 (tid<32).
    auto compute_cw = [&](int a0, int a1, int a2, int a3, int bb, int buf) {
        if (tid < 32) {
            int w = tid >> 3, k = tid & 7;
            int mm = (w == 0) ? a0 : (w == 1) ? a1 : (w == 2) ? a2 : a3;
            if (mm) {
                int slot = pb_starts[bb][w] & (RING - 1);
                float f  = pb_pxw[bb][w][0][k] + sh_gring[slot][0][k];
                float iw = pb_pxw[bb][w][1][k] + sh_gring[slot][1][k];
                float gw = pb_pxw[bb][w][2][k] + sh_gring[slot][2][k];
                float cs = sh_cring[slot][k];
                float cw = sigm_f(f) * cs + sigm_f(iw) * tanh_f(gw);
                sh_cwown[w][k] = cw;
                g_cw[buf * (WN * HN) + w * HN + j0 + k] = cw;
            }
        }
    };

    // prologue: fetch t=0 operands
    if (wid >= 14) {
        issue_pf(0, 0);
        cp_commit();
        cp_waitall();
    }
    __syncthreads();

    int nA = 0, nB = 0;
    bool early_done = false;
    // guard: if t=0 had active words (reference guarantees not), count its A-barrier
    if (pb_mask[0][0] | pb_mask[0][1] | pb_mask[0][2] | pb_mask[0][3]) nA++;

    for (int t = 0; t < TN; t++) {
        const int b = t & 1;
        // issue prefetch for t+1 into buffer b^1 (all b^1 readers of step t-1 done)
        {
            int tnn = (t + 1 < TN) ? t + 1 : t;
            if (wid >= 14) { issue_pf(tnn, b ^ 1); cp_commit(); }
        }

        const int m0 = pb_mask[b][0], m1 = pb_mask[b][1];
        const int m2 = pb_mask[b][2], m3 = pb_mask[b][3];
        const bool anyw = (m0 | m1 | m2 | m3) != 0;

        if (wid < 12) {
            // ================= group X: h stage + stage 1 =================
            if (tid < 128) {
                const float* hp = t ? (out + (size_t)(t - 1) * (2 * HN)) : h0;
                reinterpret_cast<float4*>(sh_h)[tid] =
                    __ldcg(reinterpret_cast<const float4*>(hp) + tid);
            }
            barX();                                               // h visible to X

            if (wid < 6) {
                int q = wid >> 1, half = wid & 1;
                float d[4] = {0.f, 0.f, 0.f, 0.f};
                #pragma unroll
                for (int m = 0; m < 16; m++) {
                    float hv = sh_h[lane + 32 * m];
                    #pragma unroll
                    for (int k = 0; k < 4; k++) d[k] = fmaf(hv, wreg[k][m], d[k]);
                }
                #pragma unroll
                for (int off = 16; off > 0; off >>= 1)
                    #pragma unroll
                    for (int k = 0; k < 4; k++) d[k] += __shfl_xor_sync(0xffffffffu, d[k], off);
                if (lane == 0) {
                    #pragma unroll
                    for (int k = 0; k < 4; k++) {
                        float v = pb_px[b][q][half * 4 + k] + d[k];
                        sh_act[q][half * 4 + k] = (q == 2) ? tanh_f(v) : sigm_f(v);
                    }
                }
            } else if (t > 0) {
                int q = (wid - 6) >> 1, half = (wid - 6) & 1;
                float d[4] = {0.f, 0.f, 0.f, 0.f};
                #pragma unroll
                for (int m = 0; m < 16; m++) {
                    float hv = sh_h[lane + 32 * m];
                    #pragma unroll
                    for (int k = 0; k < 4; k++) d[k] = fmaf(hv, wreg[k][m], d[k]);
                }
                #pragma unroll
                for (int off = 16; off > 0; off >>= 1)
                    #pragma unroll
                    for (int k = 0; k < 4; k++) d[k] += __shfl_xor_sync(0xffffffffu, d[k], off);
                if (lane == 0) {
                    int slot = (t - 1) & (RING - 1);
                    #pragma unroll
                    for (int k = 0; k < 4; k++)
                        sh_gring[slot][q][half * 4 + k] = d[k];
                }
            }

            if (anyw && !early_done) {
                // deferred: a length-2 word needed gring[t-1] (just computed)
                barX();                                           // gring -> warp 0
                compute_cw(m0, m1, m2, m3, b, b);
                if (wid == 0) {
                    __syncwarp();
                    if (lane == 0) red_rel_add1(&g_barA);
                }
            }
        } else {
            // ================= group Y: barrier A + c_w stage + alpha =====
            if (anyw) {
                if (tid == 384) spin_until(&g_barA, nA * NC);
                barY();                                           // A observed by all Y
                // stage full c_w (float4 ldcg; 128 threads x 1 vec per word)
                {
                    const float4* cwb = reinterpret_cast<const float4*>(&g_cw[b * (WN * HN)]);
                    int v = tid - 384;                            // 0..127
                    float4 z = make_float4(0.f, 0.f, 0.f, 0.f);
                    reinterpret_cast<float4*>(sh_cw[0])[v] = m0 ? __ldcg(cwb + 0 * 128 + v) : z;
                    reinterpret_cast<float4*>(sh_cw[1])[v] = m1 ? __ldcg(cwb + 1 * 128 + v) : z;
                    reinterpret_cast<float4*>(sh_cw[2])[v] = m2 ? __ldcg(cwb + 2 * 128 + v) : z;
                    reinterpret_cast<float4*>(sh_cw[3])[v] = m3 ? __ldcg(cwb + 3 * 128 + v) : z;
                }
                barY();                                           // c_w staged

                int p = wid - 12;
                float a2[4][2];
                #pragma unroll
                for (int w = 0; w < 4; w++)
                    #pragma unroll
                    for (int k = 0; k < 2; k++) a2[w][k] = 0.0f;
                #pragma unroll
                for (int w = 0; w < 4; w++) {
                    #pragma unroll
                    for (int m = 0; m < 16; m++) {
                        float cv = sh_cw[w][lane + 32 * m];
                        #pragma unroll
                        for (int k = 0; k < 2; k++) a2[w][k] = fmaf(cv, wua[k][m], a2[w][k]);
                    }
                }
                #pragma unroll
                for (int off = 16; off > 0; off >>= 1)
                    #pragma unroll
                    for (int w = 0; w < 4; w++)
                        #pragma unroll
                        for (int k = 0; k < 2; k++)
                            a2[w][k] += __shfl_xor_sync(0xffffffffu, a2[w][k], off);
                if (lane == 0) {
                    #pragma unroll
                    for (int w = 0; w < 4; w++)
                        #pragma unroll
                        for (int k = 0; k < 2; k++)
                            sh_alpha[w][2 * p + k] = sigm_f(pb_pxa[b][2 * p + k] + a2[w][k]);
                }
            }
            if (wid >= 14) cp_waitall();                          // t+1 operands landed
        }

        __syncthreads();                                          // MEET (X and Y join)

        // ---- combine + publish h_t / c_t (warp 0) + early B arrive ----
        if (wid == 0) {
            if (lane < CP) {
                int k = lane;
                float ig = sh_act[0][k], og = sh_act[1][k], gg = sh_act[2][k];
                float c1;
                if (anyw) {
                    float e0  = __expf(ig);
                    float den = e0, num = e0 * gg;
                    if (m0) { float ea = __expf(sh_alpha[0][k]); den += ea; num = fmaf(ea, sh_cwown[0][k], num); }
                    if (m1) { float ea = __expf(sh_alpha[1][k]); den += ea; num = fmaf(ea, sh_cwown[1][k], num); }
                    if (m2) { float ea = __expf(sh_alpha[2][k]); den += ea; num = fmaf(ea, sh_cwown[2][k], num); }
                    if (m3) { float ea = __expf(sh_alpha[3][k]); den += ea; num = fmaf(ea, sh_cwown[3][k], num); }
                    c1 = num / den;
                } else {
                    c1 = (1.0f - ig) * sh_cring[(t - 1) & (RING - 1)][k] + ig * gg;
                }
                float h1 = og * tanh_f(c1);
                sh_cring[t & (RING - 1)][k] = c1;
                out[(size_t)t * (2 * HN) + j0 + k]      = h1;
                out[(size_t)t * (2 * HN) + HN + j0 + k] = c1;
            }
            __syncwarp();                                         // order stores in-warp
            if (lane == 0) red_rel_add1(&g_barB);                 // arrive B(t) early
        }
        nB++;

        // ---- tail: early cw for step t+1 if no active word starts at t ----
        // (warp 0 computes; all threads track nA/early_done from uniform pb data)
        early_done = false;
        if (t + 1 < TN) {
            const int bn = b ^ 1;
            const int n0 = pb_mask[bn][0], n1 = pb_mask[bn][1];
            const int n2 = pb_mask[bn][2], n3 = pb_mask[bn][3];
            if (n0 | n1 | n2 | n3) {
                nA++;
                bool early = true;
                if (n0 && pb_starts[bn][0] > t - 1) early = false;
                if (n1 && pb_starts[bn][1] > t - 1) early = false;
                if (n2 && pb_starts[bn][2] > t - 1) early = false;
                if (n3 && pb_starts[bn][3] > t - 1) early = false;
                if (early) {
                    if (wid == 0) {
                        compute_cw(n0, n1, n2, n3, bn, bn);       // reads cring[t] (same warp)
                        __syncwarp();
                        if (lane == 0) red_rel_add1(&g_barA);     // early arrival at A(t+1)
                    }
                    early_done = true;
                }
            }
        }

        if (tid == 0) spin_until(&g_barB, NC * nB);               // barrier B wait
        __syncthreads();                                          // S-final
    }
}

// ---------------- launch ----------------
extern "C" void kernel_launch(void* const* d_in, const int* in_sizes, int n_in,
                              void* d_out, int out_size)
{
    const float*         x     = (const float*)d_in[0];
    const int*           wids  = (const int*)d_in[1];
    const int*           wst   = (const int*)d_in[2];
    const unsigned char* wmask = (const unsigned char*)d_in[3];
    const float*         h0    = (const float*)d_in[4];
    const float*         c0    = (const float*)d_in[5];
    const float*         emb   = (const float*)d_in[6];
    const float*         W     = (const float*)d_in[7];
    const float*         U     = (const float*)d_in[8];
    const float*         b     = (const float*)d_in[9];
    const float*         Wa    = (const float*)d_in[10];
    const float*         Ua    = (const float*)d_in[11];
    const float*         ba    = (const float*)d_in[12];
    const float*         Ww    = (const float*)d_in[13];
    const float*         Uw    = (const float*)d_in[14];
    const float*         bw    = (const float*)d_in[15];
    float*               out   = (float*)d_out;

    prep_kernel<<<1, 256>>>(wmask);
    build_active_kernel<<<(TN * WN + 255) / 256, 256>>>(wids);

    // px = x @ W + b          [4096 x 1536], K=128
    sgemm_kernel<<<dim3(G3H / 64, TN / 64), 256>>>(x, W, b, TN, G3H, DN, 0, 0);
    // pxa = x @ Wa + ba       [4096 x 512], K=128
    sgemm_kernel<<<dim3(HN / 64, TN / 64), 256>>>(x, Wa, ba, TN, HN, DN, 0, 1);
    // pxw = emb[gather] @ Ww + bw, scattered rows, K=256
    sgemm_kernel<<<dim3(G3H / 64, (TN * WN) / 64), 256>>>(emb, Ww, bw, TN * WN, G3H, EN, 1, 2);

    scan_kernel<<<NC, NTH>>>(h0, c0, wst, U, Uw, Ua, out);
}